// round 17
// baseline (speedup 1.0000x reference)
#include <cuda_runtime.h>
#include <cuda_fp16.h>
#include <math.h>
#include <stdint.h>

#define S_LEN 2048
#define HID   4096
#define KVD   1024
#define NH    32
#define NKV   8
#define HD    128

__device__ float g_Q[S_LEN * HID];
__device__ float g_K[S_LEN * KVD];
__device__ float g_V[S_LEN * KVD];
__device__ __half g_Ah[S_LEN * HID];
__device__ __half g_Wh[HID * HID];        // Wq
__device__ __half g_Wh2[KVD * HID];       // Wk
__device__ __half g_Wh3[KVD * HID];       // Wv
__device__ __half g_Wh4[HID * HID];       // Wo
__device__ __half g_Qh[S_LEN * HID];
__device__ __half g_Kh[S_LEN * KVD];
__device__ __half g_Kl[S_LEN * KVD];
__device__ __half g_Vh[S_LEN * KVD];
__device__ __half g_Vl[S_LEN * KVD];
__device__ float g_cos[S_LEN * 64];
__device__ float g_sin[S_LEN * 64];
__device__ unsigned int g_work_ctr;
__device__ unsigned int g_done_ctr;

__device__ __forceinline__ uint32_t smem_u32(const void* p) {
    uint32_t a;
    asm("{ .reg .u64 t; cvta.to.shared.u64 t, %1; cvt.u32.u64 %0, t; }"
        : "=r"(a) : "l"(p));
    return a;
}
__device__ __forceinline__ void ldsm4(uint32_t* r, uint32_t addr) {
    asm volatile("ldmatrix.sync.aligned.m8n8.x4.shared.b16 {%0,%1,%2,%3}, [%4];"
                 : "=r"(r[0]), "=r"(r[1]), "=r"(r[2]), "=r"(r[3]) : "r"(addr));
}
__device__ __forceinline__ void ldsm4t(uint32_t* r, uint32_t addr) {
    asm volatile("ldmatrix.sync.aligned.m8n8.x4.trans.shared.b16 {%0,%1,%2,%3}, [%4];"
                 : "=r"(r[0]), "=r"(r[1]), "=r"(r[2]), "=r"(r[3]) : "r"(addr));
}
__device__ __forceinline__ void mma16816(float* d, const uint32_t* a,
                                         const uint32_t* b) {
    asm volatile(
        "mma.sync.aligned.m16n8k16.row.col.f32.f16.f16.f32 "
        "{%0,%1,%2,%3},{%4,%5,%6,%7},{%8,%9},{%0,%1,%2,%3};"
        : "+f"(d[0]), "+f"(d[1]), "+f"(d[2]), "+f"(d[3])
        : "r"(a[0]), "r"(a[1]), "r"(a[2]), "r"(a[3]), "r"(b[0]), "r"(b[1]));
}
__device__ __forceinline__ void cp_async16(uint32_t dst, const void* src) {
    asm volatile("cp.async.cg.shared.global [%0], [%1], 16;"
                 :: "r"(dst), "l"(src) : "memory");
}

// ---------------------------------------------------------------------------
// fp32 -> fp16 converts
// ---------------------------------------------------------------------------
__global__ void conv_f16_kernel(const float* __restrict__ src,
                                __half* __restrict__ dst, int n)
{
    int i = (blockIdx.x * blockDim.x + threadIdx.x) * 4;
    if (i >= n) return;
    float4 v = *(const float4*)(src + i);
    __half2* dp = (__half2*)(dst + i);
    dp[0] = __floats2half2_rn(v.x, v.y);
    dp[1] = __floats2half2_rn(v.z, v.w);
}

// 4 weight matrices in one launch
__global__ void conv4_f16_kernel(
    const float* __restrict__ s0, __half* __restrict__ d0, int n0,
    const float* __restrict__ s1, __half* __restrict__ d1, int n1,
    const float* __restrict__ s2, __half* __restrict__ d2, int n2,
    const float* __restrict__ s3, __half* __restrict__ d3, int n3)
{
    int i = (blockIdx.x * blockDim.x + threadIdx.x) * 4;
    const float* s; __half* d; int ofs;
    if (i < n0) { s = s0; d = d0; ofs = i; }
    else if (i < n0 + n1) { s = s1; d = d1; ofs = i - n0; }
    else if (i < n0 + n1 + n2) { s = s2; d = d2; ofs = i - n0 - n1; }
    else if (i < n0 + n1 + n2 + n3) { s = s3; d = d3; ofs = i - n0 - n1 - n2; }
    else return;
    float4 v = *(const float4*)(s + ofs);
    __half2* dp = (__half2*)(d + ofs);
    dp[0] = __floats2half2_rn(v.x, v.y);
    dp[1] = __floats2half2_rn(v.z, v.w);
}

// ---------------------------------------------------------------------------
// 1-term fp16 GEMM: C = A * B^T (fp32 acc).
// CTA 128x128, 256 threads (8 warps, warp 64x32), BK=64, 3-stage cp.async.
// 2 CTAs/SM (110592 B smem, <=128 regs). blockIdx.z selects B/C set.
// ---------------------------------------------------------------------------
#define BK 64
#define ASTR 72
#define GT_A (128 * ASTR * 2)         // 18432
#define GT_B (128 * ASTR * 2)         // 18432
#define G1STAGE (GT_A + GT_B)         // 36864
#define G1SMEM (3 * G1STAGE)          // 110592
#define KTILES (HID / BK)             // 64

__global__ __launch_bounds__(256, 2) void gemm1_kernel(
    const __half* __restrict__ A,
    const __half* __restrict__ Bh0, float* __restrict__ C0,
    const __half* __restrict__ Bh1, float* __restrict__ C1, int N)
{
    extern __shared__ char smem[];
    const uint32_t sb = smem_u32(smem);
    const int tid  = threadIdx.x;
    const int wid  = tid >> 5;
    const int lane = tid & 31;
    const int wm   = wid & 1;
    const int wn   = wid >> 1;
    const int m0   = blockIdx.y * 128;
    const int n0   = blockIdx.x * 128;

    const __half* Bh = blockIdx.z ? Bh1 : Bh0;
    float* C = blockIdx.z ? C1 : C0;
    const __half* aSrc = A  + (size_t)m0 * HID;
    const __half* bSrc = Bh + (size_t)n0 * HID;

    auto load_stage = [&](int kt, int stage) {
        const int kc = kt * BK;
        const uint32_t sbase = sb + stage * G1STAGE;
#pragma unroll
        for (int i = 0; i < 4; i++) {
            int idx = tid + i * 256;
            int row = idx >> 3, kch = idx & 7;
            cp_async16(sbase + (uint32_t)(row * 144 + kch * 16),
                       aSrc + (size_t)row * HID + kc + kch * 8);
        }
#pragma unroll
        for (int i = 0; i < 4; i++) {
            int idx = tid + i * 256;
            int row = idx >> 3, kch = idx & 7;
            cp_async16(sbase + GT_A + (uint32_t)(row * 144 + kch * 16),
                       bSrc + (size_t)row * HID + kc + kch * 8);
        }
        asm volatile("cp.async.commit_group;" ::: "memory");
    };

    float acc[4][4][4];
#pragma unroll
    for (int i = 0; i < 4; i++)
#pragma unroll
        for (int j = 0; j < 4; j++)
#pragma unroll
            for (int q = 0; q < 4; q++) acc[i][j][q] = 0.0f;

    load_stage(0, 0);
    load_stage(1, 1);

    const int a_la  = lane & 15;
    const int a_k8  = (lane >> 4) << 3;
    const int b_r   = ((lane >> 4) << 3) + (lane & 7);
    const int b_k8  = ((lane >> 3) & 1) << 3;

    for (int kt = 0; kt < KTILES; kt++) {
        if (kt + 1 < KTILES)
            asm volatile("cp.async.wait_group 1;" ::: "memory");
        else
            asm volatile("cp.async.wait_group 0;" ::: "memory");
        __syncthreads();
        if (kt + 2 < KTILES) load_stage(kt + 2, (kt + 2) % 3);

        const uint32_t sbase = sb + (kt % 3) * G1STAGE;
        const uint32_t sA = sbase;
        const uint32_t sB = sbase + GT_A;

#pragma unroll
        for (int k16 = 0; k16 < 4; k16++) {
            uint32_t af[4][4], bf[2][4];
#pragma unroll
            for (int i = 0; i < 4; i++) {
                int arow = wm * 64 + i * 16 + a_la;
                ldsm4(af[i], sA + (uint32_t)(arow * ASTR + k16 * 16 + a_k8) * 2);
            }
#pragma unroll
            for (int jp = 0; jp < 2; jp++) {
                int brow = wn * 32 + jp * 16 + b_r;
                ldsm4(bf[jp], sB + (uint32_t)(brow * ASTR + k16 * 16 + b_k8) * 2);
            }
#pragma unroll
            for (int i = 0; i < 4; i++)
#pragma unroll
                for (int jp = 0; jp < 2; jp++) {
                    mma16816(acc[i][2 * jp],     af[i], bf[jp]);
                    mma16816(acc[i][2 * jp + 1], af[i], bf[jp] + 2);
                }
        }
    }

#pragma unroll
    for (int i = 0; i < 4; i++) {
        int row = m0 + wm * 64 + i * 16 + (lane >> 2);
#pragma unroll
        for (int j = 0; j < 4; j++) {
            int col = n0 + wn * 32 + j * 8 + (lane & 3) * 2;
            *(float2*)&C[(size_t)row * N + col] =
                make_float2(acc[i][j][0], acc[i][j][1]);
            *(float2*)&C[(size_t)(row + 8) * N + col] =
                make_float2(acc[i][j][2], acc[i][j][3]);
        }
    }
}

__global__ void rope_table_kernel(const int* __restrict__ pos)
{
    int idx = blockIdx.x * blockDim.x + threadIdx.x;
    int s = idx >> 6, i = idx & 63;
    double inv = exp(-((double)(2 * i) / 128.0) * 9.210340371976184);
    double ang = (double)pos[s] * inv;
    g_cos[idx] = (float)cos(ang);
    g_sin[idx] = (float)sin(ang);
}

// RoPE+convert: Q -> hi; K -> hi+lo; V -> hi+lo split (no rope, fused here).
__global__ void rope_split_kernel()
{
    const int s = blockIdx.x;
    const float qscale = 0.08838834764831845f;
    for (int idx = threadIdx.x; idx < (NH + 2 * NKV) * 64; idx += blockDim.x) {
        if (idx < NH * 64) {
            int head = idx >> 6, i = idx & 63;
            float c = g_cos[s * 64 + i], sn = g_sin[s * 64 + i];
            size_t base = (size_t)s * HID + head * HD;
            float x0 = g_Q[base + i];
            float x1 = g_Q[base + i + 64];
            g_Qh[base + i]      = __float2half_rn((x0 * c - x1 * sn) * qscale);
            g_Qh[base + i + 64] = __float2half_rn((x1 * c + x0 * sn) * qscale);
        } else if (idx < (NH + NKV) * 64) {
            int t = idx - NH * 64;
            int head = t >> 6, i = t & 63;
            float c = g_cos[s * 64 + i], sn = g_sin[s * 64 + i];
            size_t base = (size_t)s * KVD + head * HD;
            float x0 = g_K[base + i];
            float x1 = g_K[base + i + 64];
            float y0 = x0 * c - x1 * sn;
            float y1 = x1 * c + x0 * sn;
            __half h0 = __float2half_rn(y0);
            __half h1 = __float2half_rn(y1);
            g_Kh[base + i]      = h0;
            g_Kh[base + i + 64] = h1;
            g_Kl[base + i]      = __float2half_rn(y0 - __half2float(h0));
            g_Kl[base + i + 64] = __float2half_rn(y1 - __half2float(h1));
        } else {
            int t = idx - (NH + NKV) * 64;
            int head = t >> 6, i = t & 63;
            size_t base = (size_t)s * KVD + head * HD;
#pragma unroll
            for (int half = 0; half < 2; half++) {
                size_t p = base + i + half * 64;
                float v = g_V[p];
                __half h = __float2half_rn(v);
                g_Vh[p] = h;
                g_Vl[p] = __float2half_rn(v - __half2float(h));
            }
        }
    }
}

// ---------------------------------------------------------------------------
// Persistent flash attention. QK: Qh*Kh + Qh*Kl.  PV: Ph*Vh + Ph*Vl.
// Q fragments hoisted out of the kv-loop (loaded once per item).
// Self-resetting work counter (no zero kernel). Output fp16 -> g_Ah.
// ---------------------------------------------------------------------------
#define QSTR 136
#define FTILE (64 * QSTR * 2)
#define FSTAGE (4 * FTILE)
#define FQOFF  (2 * FSTAGE)
#define FQSZ   (128 * QSTR * 2)
#define FSMEM  (FQOFF + FQSZ)
#define FSMEM_TOT (FSMEM + 16)
#define NITEMS (NH * 16)

__global__ __launch_bounds__(256, 1) void flash_mma_kernel(
    const __half* __restrict__ Qh,
    const __half* __restrict__ Kh, const __half* __restrict__ Kl,
    const __half* __restrict__ Vh, const __half* __restrict__ Vl,
    __half* __restrict__ Oh)
{
    extern __shared__ char smem[];
    const uint32_t sb = smem_u32(smem);
    int* sWork = (int*)(smem + FSMEM);
    const int tid = threadIdx.x;
    const int lane = tid & 31;
    const int w = tid >> 5;

    const int a_la = lane & 15;
    const int a_k8 = (lane >> 4) << 3;
    const int b_r  = ((lane >> 4) << 3) + (lane & 7);
    const int b_k8 = ((lane >> 3) & 1) << 3;
    const int r0 = lane >> 2;
    const uint32_t sQh = sb + FQOFF;

    while (true) {
        if (tid == 0) *sWork = (int)atomicAdd(&g_work_ctr, 1u);
        __syncthreads();
        const int j = *sWork;
        if (j >= NITEMS) break;
        const int h  = j & 31;
        const int qb = 15 - (j >> 5);
        const int kvh = h >> 2;
        const int ntiles = 2 * (qb + 1);          // >= 2 always
        const int qrow0 = qb * 128 + w * 16;

        const __half* qsrc = Qh + (size_t)(qb * 128) * HID + h * HD;
        const __half* tsrc[4] = {
            Kh + (size_t)kvh * HD, Kl + (size_t)kvh * HD,
            Vh + (size_t)kvh * HD, Vl + (size_t)kvh * HD };

        // Q tile load (group 0)
#pragma unroll
        for (int i = 0; i < 8; i++) {
            int idx = tid + i * 256;
            int row = idx >> 4, ch = idx & 15;
            cp_async16(sb + FQOFF + (uint32_t)(row * 272 + ch * 16),
                       qsrc + (size_t)row * HID + ch * 8);
        }
        asm volatile("cp.async.commit_group;" ::: "memory");

        auto load_tile = [&](int t, int buf) {
#pragma unroll
            for (int sub = 0; sub < 4; sub++) {
                const __half* src = tsrc[sub];
                const uint32_t tb = sb + buf * FSTAGE + sub * FTILE;
#pragma unroll
                for (int i = 0; i < 4; i++) {
                    int idx = tid + i * 256;
                    int row = idx >> 4, ch = idx & 15;
                    cp_async16(tb + (uint32_t)(row * 272 + ch * 16),
                               src + (size_t)(t * 64 + row) * KVD + ch * 8);
                }
            }
            asm volatile("cp.async.commit_group;" ::: "memory");
        };

        load_tile(0, 0);                           // group 1

        // Wait for Q (group 0 complete; tile0 may still be in flight)
        asm volatile("cp.async.wait_group 1;" ::: "memory");
        __syncthreads();

        // Hoisted Q fragments (constant over all kv tiles of this item)
        uint32_t aq[8][4];
#pragma unroll
        for (int ks = 0; ks < 8; ks++) {
            uint32_t aoff = (uint32_t)((w * 16 + a_la) * QSTR + ks * 16 + a_k8) * 2;
            ldsm4(aq[ks], sQh + aoff);
        }

        load_tile(1, 1);                           // group 2

        float m[2] = {-1e30f, -1e30f}, l[2] = {0.0f, 0.0f};
        float o[16][4];
#pragma unroll
        for (int jj = 0; jj < 16; jj++)
#pragma unroll
            for (int q = 0; q < 4; q++) o[jj][q] = 0.0f;

        for (int t = 0; t < ntiles; t++) {
            if (t + 1 < ntiles)
                asm volatile("cp.async.wait_group 1;" ::: "memory");
            else
                asm volatile("cp.async.wait_group 0;" ::: "memory");
            __syncthreads();

            const uint32_t stg = sb + (t & 1) * FSTAGE;
            const uint32_t sKh = stg, sKl = stg + FTILE;
            const uint32_t sVh = stg + 2 * FTILE, sVl = stg + 3 * FTILE;

            const bool skip = (qrow0 + 15) < t * 64;
            if (!skip) {
                float sc[8][4];
#pragma unroll
                for (int nt = 0; nt < 8; nt++)
#pragma unroll
                    for (int q = 0; q < 4; q++) sc[nt][q] = 0.0f;

#pragma unroll
                for (int ks = 0; ks < 8; ks++) {
                    uint32_t bh[4][4], bl[4][4];
#pragma unroll
                    for (int np = 0; np < 4; np++) {
                        uint32_t boff = (uint32_t)((np * 16 + b_r) * QSTR + ks * 16 + b_k8) * 2;
                        ldsm4(bh[np], sKh + boff);
                        ldsm4(bl[np], sKl + boff);
                    }
#pragma unroll
                    for (int np = 0; np < 4; np++) {
                        mma16816(sc[2 * np],     aq[ks], bh[np]);
                        mma16816(sc[2 * np + 1], aq[ks], bh[np] + 2);
                    }
#pragma unroll
                    for (int np = 0; np < 4; np++) {
                        mma16816(sc[2 * np],     aq[ks], bl[np]);
                        mma16816(sc[2 * np + 1], aq[ks], bl[np] + 2);
                    }
                }

                if (t * 64 + 63 > qrow0) {
#pragma unroll
                    for (int nt = 0; nt < 8; nt++)
#pragma unroll
                        for (int e = 0; e < 4; e++) {
                            int col = t * 64 + nt * 8 + (lane & 3) * 2 + (e & 1);
                            int row = qrow0 + r0 + ((e >> 1) << 3);
                            if (col > row) sc[nt][e] = -1e30f;
                        }
                }

#pragma unroll
                for (int rr = 0; rr < 2; rr++) {
                    float mt = -1e30f;
#pragma unroll
                    for (int nt = 0; nt < 8; nt++)
                        mt = fmaxf(mt, fmaxf(sc[nt][rr * 2], sc[nt][rr * 2 + 1]));
                    mt = fmaxf(mt, __shfl_xor_sync(0xffffffffu, mt, 1));
                    mt = fmaxf(mt, __shfl_xor_sync(0xffffffffu, mt, 2));
                    float mn = fmaxf(m[rr], mt);
                    float alpha = __expf(m[rr] - mn);
                    m[rr] = mn;
                    float sum = 0.0f;
#pragma unroll
                    for (int nt = 0; nt < 8; nt++) {
                        float p0 = __expf(sc[nt][rr * 2]     - mn);
                        float p1 = __expf(sc[nt][rr * 2 + 1] - mn);
                        sc[nt][rr * 2] = p0; sc[nt][rr * 2 + 1] = p1;
                        sum += p0 + p1;
                    }
                    sum += __shfl_xor_sync(0xffffffffu, sum, 1);
                    sum += __shfl_xor_sync(0xffffffffu, sum, 2);
                    l[rr] = l[rr] * alpha + sum;
#pragma unroll
                    for (int jj = 0; jj < 16; jj++) {
                        o[jj][rr * 2]     *= alpha;
                        o[jj][rr * 2 + 1] *= alpha;
                    }
                }

                uint32_t ph[4][4];
#pragma unroll
                for (int ks2 = 0; ks2 < 4; ks2++)
#pragma unroll
                    for (int half = 0; half < 2; half++) {
                        int nt = 2 * ks2 + half;
#pragma unroll
                        for (int rr = 0; rr < 2; rr++) {
                            __half2 hp = __floats2half2_rn(sc[nt][rr * 2],
                                                           sc[nt][rr * 2 + 1]);
                            ph[ks2][half * 2 + rr] = *(uint32_t*)&hp;
                        }
                    }

#pragma unroll
                for (int ks2 = 0; ks2 < 4; ks2++) {
#pragma unroll
                    for (int g = 0; g < 2; g++) {
                        uint32_t vh[4][4], vl[4][4];
#pragma unroll
                        for (int q = 0; q < 4; q++) {
                            int np = g * 4 + q;
                            uint32_t voff = (uint32_t)((ks2 * 16 + a_la) * QSTR + np * 16 + a_k8) * 2;
                            ldsm4t(vh[q], sVh + voff);
                            ldsm4t(vl[q], sVl + voff);
                        }
#pragma unroll
                        for (int q = 0; q < 4; q++) {
                            int np = g * 4 + q;
                            mma16816(o[2 * np],     ph[ks2], vh[q]);
                            mma16816(o[2 * np + 1], ph[ks2], vh[q] + 2);
                        }
#pragma unroll
                        for (int q = 0; q < 4; q++) {
                            int np = g * 4 + q;
                            mma16816(o[2 * np],     ph[ks2], vl[q]);
                            mma16816(o[2 * np + 1], ph[ks2], vl[q] + 2);
                        }
                    }
                }
            }
            __syncthreads();
            if (t + 2 < ntiles) load_tile(t + 2, t & 1);
        }

        // epilogue: normalize, convert to fp16, write to O-proj input
#pragma unroll
        for (int rr = 0; rr < 2; rr++) {
            float inv = 1.0f / l[rr];
            int grow = qrow0 + r0 + rr * 8;
#pragma unroll
            for (int jj = 0; jj < 16; jj++) {
                int col = h * HD + jj * 8 + (lane & 3) * 2;
                __half2 hv = __floats2half2_rn(o[jj][rr * 2] * inv,
                                               o[jj][rr * 2 + 1] * inv);
                *(__half2*)&Oh[(size_t)grow * HID + col] = hv;
            }
        }
    }

    // self-reset for next graph replay (deterministic: last CTA resets)
    if (tid == 0) {
        if (atomicAdd(&g_done_ctr, 1u) == (unsigned)(gridDim.x - 1)) {
            atomicExch(&g_work_ctr, 0u);
            atomicExch(&g_done_ctr, 0u);
        }
    }
}

extern "C" void kernel_launch(void* const* d_in, const int* in_sizes, int n_in,
                              void* d_out, int out_size)
{
    const float* hidden = (const float*)d_in[0];
    const int*   pos    = (const int*)d_in[1];
    const float* Wq     = (const float*)d_in[2];
    const float* Wk     = (const float*)d_in[3];
    const float* Wv     = (const float*)d_in[4];
    const float* Wo     = (const float*)d_in[5];
    float* out = (float*)d_out;

    float *qp, *kp, *vp;
    __half *ah, *wh, *wh2, *wh3, *wh4;
    __half *qhp, *khp, *klp, *vhp, *vlp;
    cudaGetSymbolAddress((void**)&qp,  g_Q);
    cudaGetSymbolAddress((void**)&kp,  g_K);
    cudaGetSymbolAddress((void**)&vp,  g_V);
    cudaGetSymbolAddress((void**)&ah,  g_Ah);
    cudaGetSymbolAddress((void**)&wh,  g_Wh);
    cudaGetSymbolAddress((void**)&wh2, g_Wh2);
    cudaGetSymbolAddress((void**)&wh3, g_Wh3);
    cudaGetSymbolAddress((void**)&wh4, g_Wh4);
    cudaGetSymbolAddress((void**)&qhp, g_Qh);
    cudaGetSymbolAddress((void**)&khp, g_Kh);
    cudaGetSymbolAddress((void**)&klp, g_Kl);
    cudaGetSymbolAddress((void**)&vhp, g_Vh);
    cudaGetSymbolAddress((void**)&vlp, g_Vl);

    cudaFuncSetAttribute(gemm1_kernel,
                         cudaFuncAttributeMaxDynamicSharedMemorySize, G1SMEM);
    cudaFuncSetAttribute(flash_mma_kernel,
                         cudaFuncAttributeMaxDynamicSharedMemorySize, FSMEM_TOT);

    const int NA  = S_LEN * HID;
    const int NWQ = HID * HID;
    const int NWK = KVD * HID;
    const int NW_ALL = 2 * NWQ + 2 * NWK;

    // (1) act conv, (2) all-weights conv, (3) rope table,
    // (4) gemm1 Q  <- ncu capture
    conv_f16_kernel<<<NA / 4 / 256, 256>>>(hidden, ah, NA);
    conv4_f16_kernel<<<(NW_ALL / 4 + 255) / 256, 256>>>(
        Wq, wh, NWQ, Wk, wh2, NWK, Wv, wh3, NWK, Wo, wh4, NWQ);
    rope_table_kernel<<<S_LEN * 64 / 256, 256>>>(pos);
    gemm1_kernel<<<dim3(HID / 128, S_LEN / 128, 1), 256, G1SMEM>>>(
        ah, wh, qp, wh, qp, HID);

    // K + V projections, fused
    gemm1_kernel<<<dim3(KVD / 128, S_LEN / 128, 2), 256, G1SMEM>>>(
        ah, wh2, kp, wh3, vp, KVD);

    // RoPE + Q/K/V fp16 conversion (V split folded in)
    rope_split_kernel<<<S_LEN, 256>>>();

    // flash attention (persistent; self-resetting counter)
    flash_mma_kernel<<<148, 256, FSMEM_TOT>>>(
        qhp, khp, klp, vhp, vlp, ah);

    // O projection
    gemm1_kernel<<<dim3(HID / 128, S_LEN / 128, 1), 256, G1SMEM>>>(
        ah, wh4, out, wh4, out, HID);
}